// round 9
// baseline (speedup 1.0000x reference)
#include <cuda_runtime.h>

// ---------------------------------------------------------------------------
// GRU encoder-decoder, persistent per-CTA recurrence, f32x2-packed compute.
// R7 (= R6 resubmit; infra failure last round): activations stored DUPLICATED
// in smem ([k][2*row]) so f32x2 operands load directly via LDS.128 -- zero
// dup-MOVs on the fma pipe. Weights rz-interleaved (LDS.128 feeds r+z pairs,
// LDS.64 feeds n). NT=256, thread tile = 2 units x 4 rows. Double-buffered h.
// ---------------------------------------------------------------------------

typedef unsigned long long u64;

#define Hh     64
#define G3     192
#define ROWS   32
#define NT     256
#define TSEQ   256
#define NINP   6

// SMEM float offsets
#define OFF_WX0RZ  0        // [6][128]
#define OFF_WX0N   768      // [6][64]
#define OFF_WH0RZ  1152     // [64][128]
#define OFF_WH0N   9344     // [64][64]
#define OFF_WX1RZ  13440    // [64][128]
#define OFF_WX1N   21632    // [64][64]
#define OFF_WH1RZ  25728    // [64][128]
#define OFF_WH1N   33920    // [64][64]
#define OFF_HS0    38016    // [2][64][64] row-duplicated
#define OFF_HS1    46208    // [2][64][64]
#define OFF_XS     54400    // [2][8][64]  row-duplicated
#define OFF_OW     55424    // [64]
#define OFF_OB     55488    // [1]
#define SMEM_FLOATS 55492   // 221,968 bytes

#define HBUF 4096           // floats per h double-buffer slot
#define XBUF 512            // floats per x double-buffer slot

__device__ __forceinline__ u64 pk2(float lo, float hi) {
    u64 r; asm("mov.b64 %0, {%1,%2};" : "=l"(r) : "f"(lo), "f"(hi)); return r;
}
__device__ __forceinline__ float2 up2(u64 v) {
    float2 r; asm("mov.b64 {%0,%1}, %2;" : "=f"(r.x), "=f"(r.y) : "l"(v)); return r;
}
#define FFMA2(acc, a, b) \
    asm("fma.rn.f32x2 %0, %1, %2, %0;" : "+l"(acc) : "l"(a), "l"(b))

__device__ __forceinline__ float sigf(float x) {
    return 1.0f / (1.0f + __expf(-x));
}
__device__ __forceinline__ float tanhfast(float x) {
    float e = __expf(-2.0f * fabsf(x));
    float t = (1.0f - e) / (1.0f + e);
    return copysignf(t, x);
}

// Split-transpose W[192][K] (row-major) into:
//   rz[k*128 + ut*4 + gate*2 + lane]  (gates r,z)
//   n [k*64  + ut*2 + lane]           (gate n)
__device__ __forceinline__ void load_w_split(float* dstRZ, float* dstN,
                                             const float* __restrict__ src,
                                             int K, int tid) {
    for (int idx = tid; idx < G3 * K; idx += NT) {
        int g = idx / K;
        int k = idx - g * K;
        int gate = g >> 6;          // 0=r,1=z,2=n
        int j    = g & 63;
        int ut   = j >> 1;
        int lane = j & 1;
        float v = src[idx];
        if (gate < 2) dstRZ[k * 128 + ut * 4 + gate * 2 + lane] = v;
        else          dstN [k * 64  + ut * 2 + lane]            = v;
    }
}

// GRU cell for this thread's [2 units (f32x2 packed) x 4 rows] tile.
// xsrc/hsrc/hdst row-DUPLICATED: value (k,row) lives at [k*64 + 2*row + {0,1}].
template<int KIN>
__device__ __forceinline__ void gru_tile2(
    const float* __restrict__ Wxrz, const float* __restrict__ Wxn,
    const float* __restrict__ Whrz, const float* __restrict__ Whn,
    const float* __restrict__ xsrc, const float* __restrict__ hsrc,
    float* __restrict__ hdst,
    u64 br2, u64 bz2, u64 bi2, u64 bh2,
    int ut, int r0)
{
    u64 ar[4], az[4], ai[4], ah[4];
#pragma unroll
    for (int rr = 0; rr < 4; rr++) { ar[rr] = br2; az[rr] = bz2; ai[rr] = bi2; ah[rr] = bh2; }

    const float* wxrz = Wxrz + ut * 4;
    const float* wxn  = Wxn  + ut * 2;
    const float* xp   = xsrc + 2 * r0;
#pragma unroll
    for (int k = 0; k < KIN; k++) {
        ulonglong2 ha = *(const ulonglong2*)(xp + k * 64);       // rows r0,r0+1 dup
        ulonglong2 hb = *(const ulonglong2*)(xp + k * 64 + 4);   // rows r0+2,r0+3
        ulonglong2 wv = *(const ulonglong2*)(wxrz + k * 128);    // (r-pair, z-pair)
        u64 wn = *(const u64*)(wxn + k * 64);
        FFMA2(ar[0], wv.x, ha.x); FFMA2(ar[1], wv.x, ha.y);
        FFMA2(ar[2], wv.x, hb.x); FFMA2(ar[3], wv.x, hb.y);
        FFMA2(az[0], wv.y, ha.x); FFMA2(az[1], wv.y, ha.y);
        FFMA2(az[2], wv.y, hb.x); FFMA2(az[3], wv.y, hb.y);
        FFMA2(ai[0], wn,   ha.x); FFMA2(ai[1], wn,   ha.y);
        FFMA2(ai[2], wn,   hb.x); FFMA2(ai[3], wn,   hb.y);
    }

    const float* whrz = Whrz + ut * 4;
    const float* whn  = Whn  + ut * 2;
    const float* hp   = hsrc + 2 * r0;
#pragma unroll 8
    for (int k = 0; k < Hh; k++) {
        ulonglong2 ha = *(const ulonglong2*)(hp + k * 64);
        ulonglong2 hb = *(const ulonglong2*)(hp + k * 64 + 4);
        ulonglong2 wv = *(const ulonglong2*)(whrz + k * 128);
        u64 wn = *(const u64*)(whn + k * 64);
        FFMA2(ar[0], wv.x, ha.x); FFMA2(ar[1], wv.x, ha.y);
        FFMA2(ar[2], wv.x, hb.x); FFMA2(ar[3], wv.x, hb.y);
        FFMA2(az[0], wv.y, ha.x); FFMA2(az[1], wv.y, ha.y);
        FFMA2(az[2], wv.y, hb.x); FFMA2(az[3], wv.y, hb.y);
        FFMA2(ah[0], wn,   ha.x); FFMA2(ah[1], wn,   ha.y);
        FFMA2(ah[2], wn,   hb.x); FFMA2(ah[3], wn,   hb.y);
    }

    // epilogue: r,z sigmoid; n = tanh(in + r*hn); h' = n + z*(h_old - n)
    const int j0 = ut * 2;
    float o0[4], o1[4];
#pragma unroll
    for (int rr = 0; rr < 4; rr++) {
        float ho0 = hsrc[j0 * 64 + 2 * (r0 + rr)];
        float ho1 = hsrc[(j0 + 1) * 64 + 2 * (r0 + rr)];
        float2 arv = up2(ar[rr]), azv = up2(az[rr]);
        float2 aiv = up2(ai[rr]), ahv = up2(ah[rr]);
        {
            float r = sigf(arv.x), z = sigf(azv.x);
            float n = tanhfast(fmaf(r, ahv.x, aiv.x));
            o0[rr] = fmaf(z, ho0 - n, n);
        }
        {
            float r = sigf(arv.y), z = sigf(azv.y);
            float n = tanhfast(fmaf(r, ahv.y, aiv.y));
            o1[rr] = fmaf(z, ho1 - n, n);
        }
    }
    // duplicated stores: 2x STS.128 per unit
    *(ulonglong2*)(hdst + j0 * 64 + 2 * r0) =
        make_ulonglong2(pk2(o0[0], o0[0]), pk2(o0[1], o0[1]));
    *(ulonglong2*)(hdst + j0 * 64 + 2 * r0 + 4) =
        make_ulonglong2(pk2(o0[2], o0[2]), pk2(o0[3], o0[3]));
    *(ulonglong2*)(hdst + (j0 + 1) * 64 + 2 * r0) =
        make_ulonglong2(pk2(o1[0], o1[0]), pk2(o1[1], o1[1]));
    *(ulonglong2*)(hdst + (j0 + 1) * 64 + 2 * r0 + 4) =
        make_ulonglong2(pk2(o1[2], o1[2]), pk2(o1[3], o1[3]));
}

extern __shared__ float sm[];

__global__ __launch_bounds__(NT, 1)
void gru_kernel(
    const float* __restrict__ x,
    const float* __restrict__ eWih0, const float* __restrict__ eWhh0,
    const float* __restrict__ ebih0, const float* __restrict__ ebhh0,
    const float* __restrict__ eWih1, const float* __restrict__ eWhh1,
    const float* __restrict__ ebih1, const float* __restrict__ ebhh1,
    const float* __restrict__ dWih0, const float* __restrict__ dWhh0,
    const float* __restrict__ dbih0, const float* __restrict__ dbhh0,
    const float* __restrict__ dWih1, const float* __restrict__ dWhh1,
    const float* __restrict__ dbih1, const float* __restrict__ dbhh1,
    const float* __restrict__ outW, const float* __restrict__ outb,
    float* __restrict__ out, int Bn, int TL)
{
    const int tid = threadIdx.x;
    const int b0  = blockIdx.x * ROWS;

    float* Wx0rz = sm + OFF_WX0RZ;  float* Wx0n = sm + OFF_WX0N;
    float* Wh0rz = sm + OFF_WH0RZ;  float* Wh0n = sm + OFF_WH0N;
    float* Wx1rz = sm + OFF_WX1RZ;  float* Wx1n = sm + OFF_WX1N;
    float* Wh1rz = sm + OFF_WH1RZ;  float* Wh1n = sm + OFF_WH1N;
    float* hs0 = sm + OFF_HS0;
    float* hs1 = sm + OFF_HS1;
    float* xs  = sm + OFF_XS;
    float* sOW = sm + OFF_OW;
    float* sOB = sm + OFF_OB;

    const int rt = tid & 7;          // row tile (4 rows)
    const int ut = tid >> 3;         // unit tile (2 units, f32x2 packed)
    const int r0 = rt * 4;
    const int j0 = ut * 2;

    // ---- stage encoder weights ----
    load_w_split(Wx0rz, Wx0n, eWih0, NINP, tid);
    load_w_split(Wh0rz, Wh0n, eWhh0, Hh, tid);
    load_w_split(Wx1rz, Wx1n, eWih1, Hh, tid);
    load_w_split(Wh1rz, Wh1n, eWhh1, Hh, tid);
    for (int i = tid; i < HBUF; i += NT) {
        hs0[i] = 0.0f; hs0[HBUF + i] = 0.0f;
        hs1[i] = 0.0f; hs1[HBUF + i] = 0.0f;
    }

    // ---- encoder bias pairs in registers ----
    u64 b0r, b0z, b0i, b0h, b1r, b1z, b1i, b1h;
    {
        float2 a, b;
        a = *(const float2*)(ebih0 + j0);        b = *(const float2*)(ebhh0 + j0);
        b0r = pk2(a.x + b.x, a.y + b.y);
        a = *(const float2*)(ebih0 + 64 + j0);   b = *(const float2*)(ebhh0 + 64 + j0);
        b0z = pk2(a.x + b.x, a.y + b.y);
        a = *(const float2*)(ebih0 + 128 + j0);  b0i = pk2(a.x, a.y);
        b = *(const float2*)(ebhh0 + 128 + j0);  b0h = pk2(b.x, b.y);
        a = *(const float2*)(ebih1 + j0);        b = *(const float2*)(ebhh1 + j0);
        b1r = pk2(a.x + b.x, a.y + b.y);
        a = *(const float2*)(ebih1 + 64 + j0);   b = *(const float2*)(ebhh1 + 64 + j0);
        b1z = pk2(a.x + b.x, a.y + b.y);
        a = *(const float2*)(ebih1 + 128 + j0);  b1i = pk2(a.x, a.y);
        b = *(const float2*)(ebhh1 + 128 + j0);  b1h = pk2(b.x, b.y);
    }

    // prestage x for t=0 into buffer 0 (duplicated layout)
    const int xi = tid >> 5, xr = tid & 31;
    if (tid < NINP * ROWS) {
        float v = (b0 + xr < Bn)
            ? x[(size_t)(b0 + xr) * (TSEQ * NINP) + xi] : 0.0f;
        *(u64*)(xs + xi * 64 + 2 * xr) = pk2(v, v);
    }
    __syncthreads();

    // ---- encoder: 256 steps ----
    int cur = 0;
    for (int t = 0; t < TSEQ; t++) {
        float xreg = 0.0f;
        if (tid < NINP * ROWS && t + 1 < TSEQ && b0 + xr < Bn)
            xreg = x[(size_t)(b0 + xr) * (TSEQ * NINP) + (size_t)(t + 1) * NINP + xi];
        int nxt = cur ^ 1;
        gru_tile2<NINP>(Wx0rz, Wx0n, Wh0rz, Wh0n,
                        xs + cur * XBUF, hs0 + cur * HBUF, hs0 + nxt * HBUF,
                        b0r, b0z, b0i, b0h, ut, r0);
        if (tid < NINP * ROWS)
            *(u64*)(xs + nxt * XBUF + xi * 64 + 2 * xr) = pk2(xreg, xreg);
        __syncthreads();
        gru_tile2<Hh>(Wx1rz, Wx1n, Wh1rz, Wh1n,
                      hs0 + nxt * HBUF, hs1 + cur * HBUF, hs1 + nxt * HBUF,
                      b1r, b1z, b1i, b1h, ut, r0);
        cur = nxt;
        __syncthreads();
    }

    // ---- swap in decoder weights ----
    load_w_split(Wx0rz, Wx0n, dWih0, 1, tid);
    load_w_split(Wh0rz, Wh0n, dWhh0, Hh, tid);
    load_w_split(Wx1rz, Wx1n, dWih1, Hh, tid);
    load_w_split(Wh1rz, Wh1n, dWhh1, Hh, tid);
    if (tid < Hh) sOW[tid] = outW[tid];
    if (tid == 0) sOB[0] = outb[0];
    if (tid < ROWS) *(u64*)(xs + 2 * tid) = pk2(0.0f, 0.0f);   // prev cv = 0
    {
        float2 a, b;
        a = *(const float2*)(dbih0 + j0);        b = *(const float2*)(dbhh0 + j0);
        b0r = pk2(a.x + b.x, a.y + b.y);
        a = *(const float2*)(dbih0 + 64 + j0);   b = *(const float2*)(dbhh0 + 64 + j0);
        b0z = pk2(a.x + b.x, a.y + b.y);
        a = *(const float2*)(dbih0 + 128 + j0);  b0i = pk2(a.x, a.y);
        b = *(const float2*)(dbhh0 + 128 + j0);  b0h = pk2(b.x, b.y);
        a = *(const float2*)(dbih1 + j0);        b = *(const float2*)(dbhh1 + j0);
        b1r = pk2(a.x + b.x, a.y + b.y);
        a = *(const float2*)(dbih1 + 64 + j0);   b = *(const float2*)(dbhh1 + 64 + j0);
        b1z = pk2(a.x + b.x, a.y + b.y);
        a = *(const float2*)(dbih1 + 128 + j0);  b1i = pk2(a.x, a.y);
        b = *(const float2*)(dbhh1 + 128 + j0);  b1h = pk2(b.x, b.y);
    }
    __syncthreads();

    // ---- decoder: TL autoregressive steps ----
    for (int s = 0; s < TL; s++) {
        int nxt = cur ^ 1;
        gru_tile2<1>(Wx0rz, Wx0n, Wh0rz, Wh0n,
                     xs, hs0 + cur * HBUF, hs0 + nxt * HBUF,
                     b0r, b0z, b0i, b0h, ut, r0);
        __syncthreads();
        gru_tile2<Hh>(Wx1rz, Wx1n, Wh1rz, Wh1n,
                      hs0 + nxt * HBUF, hs1 + cur * HBUF, hs1 + nxt * HBUF,
                      b1r, b1z, b1i, b1h, ut, r0);
        __syncthreads();
        if (tid < ROWS) {
            float acc = sOB[0];
            const float* hp = hs1 + nxt * HBUF + 2 * tid;
            #pragma unroll 8
            for (int j = 0; j < Hh; j++)
                acc = fmaf(sOW[j], hp[j * 64], acc);
            if (b0 + tid < Bn)
                out[(size_t)(b0 + tid) * TL + s] = acc;
            *(u64*)(xs + 2 * tid) = pk2(acc, acc);
        }
        cur = nxt;
        __syncthreads();
    }
}

extern "C" void kernel_launch(void* const* d_in, const int* in_sizes, int n_in,
                              void* d_out, int out_size) {
    const float* x      = (const float*)d_in[0];
    const float* eWih0  = (const float*)d_in[1];
    const float* eWhh0  = (const float*)d_in[2];
    const float* ebih0  = (const float*)d_in[3];
    const float* ebhh0  = (const float*)d_in[4];
    const float* eWih1  = (const float*)d_in[5];
    const float* eWhh1  = (const float*)d_in[6];
    const float* ebih1  = (const float*)d_in[7];
    const float* ebhh1  = (const float*)d_in[8];
    const float* dWih0  = (const float*)d_in[9];
    const float* dWhh0  = (const float*)d_in[10];
    const float* dbih0  = (const float*)d_in[11];
    const float* dbhh0  = (const float*)d_in[12];
    const float* dWih1  = (const float*)d_in[13];
    const float* dWhh1  = (const float*)d_in[14];
    const float* dbih1  = (const float*)d_in[15];
    const float* dbhh1  = (const float*)d_in[16];
    const float* outW   = (const float*)d_in[17];
    const float* outb   = (const float*)d_in[18];

    int B  = in_sizes[0] / (TSEQ * NINP);
    int TL = out_size / B;                       // 180
    int grid = (B + ROWS - 1) / ROWS;            // 128
    size_t smem = SMEM_FLOATS * sizeof(float);   // ~222 KB

    cudaFuncSetAttribute(gru_kernel,
                         cudaFuncAttributeMaxDynamicSharedMemorySize,
                         (int)smem);

    gru_kernel<<<grid, NT, smem>>>(
        x, eWih0, eWhh0, ebih0, ebhh0, eWih1, eWhh1, ebih1, ebhh1,
        dWih0, dWhh0, dbih0, dbhh0, dWih1, dWhh1, dbih1, dbhh1,
        outW, outb, (float*)d_out, B, TL);
}

// round 11
// speedup vs baseline: 1.4155x; 1.4155x over previous
#include <cuda_runtime.h>

// ---------------------------------------------------------------------------
// GRU encoder-decoder, persistent per-CTA recurrence, f32x2-packed compute.
// R10: duplicated-activation layout, DE-INTERLEAVED so both row-pair loads
// (ha/hb) are LDS.128 at byte 16*rt (banks 4rt..4rt+3 = conflict-free, same
// pattern as the proven R2 h-load). Inner k-body = 4 LDS + 12 FFMA2, zero
// dup-MOVs. Unroll 4 to keep regs ~110. NT=256, tile 2 units x 4 rows.
//
// Dup layout per k-row (64 floats):
//   A chunk rt (floats k*64 + 4rt)      = (v[4rt],v[4rt],v[4rt+1],v[4rt+1])
//   B chunk rt (floats k*64 + 32 + 4rt) = (v[4rt+2],v[4rt+2],v[4rt+3],v[4rt+3])
// Writer for single row r: off = 32*((r>>1)&1) + 4*(r>>2) + 2*(r&1).
// ---------------------------------------------------------------------------

typedef unsigned long long u64;

#define Hh     64
#define G3     192
#define ROWS   32
#define NT     256
#define TSEQ   256
#define NINP   6

// SMEM float offsets
#define OFF_WX0RZ  0        // [6][128]
#define OFF_WX0N   768      // [6][64]
#define OFF_WH0RZ  1152     // [64][128]
#define OFF_WH0N   9344     // [64][64]
#define OFF_WX1RZ  13440    // [64][128]
#define OFF_WX1N   21632    // [64][64]
#define OFF_WH1RZ  25728    // [64][128]
#define OFF_WH1N   33920    // [64][64]
#define OFF_HS0    38016    // [2][64][64] dup, de-interleaved
#define OFF_HS1    46208    // [2][64][64]
#define OFF_XS     54400    // [2][8][64]
#define OFF_OW     55424    // [64]
#define OFF_OB     55488    // [1]
#define SMEM_FLOATS 55492   // 221,968 bytes

#define HBUF 4096
#define XBUF 512

__device__ __forceinline__ u64 pk2(float lo, float hi) {
    u64 r; asm("mov.b64 %0, {%1,%2};" : "=l"(r) : "f"(lo), "f"(hi)); return r;
}
__device__ __forceinline__ float2 up2(u64 v) {
    float2 r; asm("mov.b64 {%0,%1}, %2;" : "=f"(r.x), "=f"(r.y) : "l"(v)); return r;
}
#define FFMA2(acc, a, b) \
    asm("fma.rn.f32x2 %0, %1, %2, %0;" : "+l"(acc) : "l"(a), "l"(b))

__device__ __forceinline__ float sigf(float x) {
    return 1.0f / (1.0f + __expf(-x));
}
__device__ __forceinline__ float tanhfast(float x) {
    float e = __expf(-2.0f * fabsf(x));
    float t = (1.0f - e) / (1.0f + e);
    return copysignf(t, x);
}

// dup-layout float offset within a k-row for single row r
__device__ __forceinline__ int dup_off(int r) {
    return 32 * ((r >> 1) & 1) + 4 * (r >> 2) + 2 * (r & 1);
}

// Split-transpose W[192][K] (row-major) into:
//   rz[k*128 + ut*4 + gate*2 + lane]  (gates r,z)
//   n [k*64  + ut*2 + lane]           (gate n)
__device__ __forceinline__ void load_w_split(float* dstRZ, float* dstN,
                                             const float* __restrict__ src,
                                             int K, int tid) {
    for (int idx = tid; idx < G3 * K; idx += NT) {
        int g = idx / K;
        int k = idx - g * K;
        int gate = g >> 6;          // 0=r,1=z,2=n
        int j    = g & 63;
        int ut   = j >> 1;
        int lane = j & 1;
        float v = src[idx];
        if (gate < 2) dstRZ[k * 128 + ut * 4 + gate * 2 + lane] = v;
        else          dstN [k * 64  + ut * 2 + lane]            = v;
    }
}

// GRU cell for this thread's [2 units (f32x2 packed) x 4 rows] tile.
// xsrc/hsrc/hdst in dup de-interleaved layout (see header).
template<int KIN>
__device__ __forceinline__ void gru_tile2(
    const float* __restrict__ Wxrz, const float* __restrict__ Wxn,
    const float* __restrict__ Whrz, const float* __restrict__ Whn,
    const float* __restrict__ xsrc, const float* __restrict__ hsrc,
    float* __restrict__ hdst,
    u64 br2, u64 bz2, u64 bi2, u64 bh2,
    int ut, int rt)
{
    u64 ar[4], az[4], ai[4], ah[4];
#pragma unroll
    for (int rr = 0; rr < 4; rr++) { ar[rr] = br2; az[rr] = bz2; ai[rr] = bi2; ah[rr] = bh2; }

    const float* wxrz = Wxrz + ut * 4;
    const float* wxn  = Wxn  + ut * 2;
    const float* xpA  = xsrc + 4 * rt;        // rows r0,r0+1 (dup pairs)
    const float* xpB  = xsrc + 32 + 4 * rt;   // rows r0+2,r0+3
#pragma unroll
    for (int k = 0; k < KIN; k++) {
        ulonglong2 ha = *(const ulonglong2*)(xpA + k * 64);
        ulonglong2 hb = *(const ulonglong2*)(xpB + k * 64);
        ulonglong2 wv = *(const ulonglong2*)(wxrz + k * 128);   // (r-pair, z-pair)
        u64 wn = *(const u64*)(wxn + k * 64);
        FFMA2(ar[0], wv.x, ha.x); FFMA2(ar[1], wv.x, ha.y);
        FFMA2(ar[2], wv.x, hb.x); FFMA2(ar[3], wv.x, hb.y);
        FFMA2(az[0], wv.y, ha.x); FFMA2(az[1], wv.y, ha.y);
        FFMA2(az[2], wv.y, hb.x); FFMA2(az[3], wv.y, hb.y);
        FFMA2(ai[0], wn,   ha.x); FFMA2(ai[1], wn,   ha.y);
        FFMA2(ai[2], wn,   hb.x); FFMA2(ai[3], wn,   hb.y);
    }

    const float* whrz = Whrz + ut * 4;
    const float* whn  = Whn  + ut * 2;
    const float* hpA  = hsrc + 4 * rt;
    const float* hpB  = hsrc + 32 + 4 * rt;
#pragma unroll 4
    for (int k = 0; k < Hh; k++) {
        ulonglong2 ha = *(const ulonglong2*)(hpA + k * 64);
        ulonglong2 hb = *(const ulonglong2*)(hpB + k * 64);
        ulonglong2 wv = *(const ulonglong2*)(whrz + k * 128);
        u64 wn = *(const u64*)(whn + k * 64);
        FFMA2(ar[0], wv.x, ha.x); FFMA2(ar[1], wv.x, ha.y);
        FFMA2(ar[2], wv.x, hb.x); FFMA2(ar[3], wv.x, hb.y);
        FFMA2(az[0], wv.y, ha.x); FFMA2(az[1], wv.y, ha.y);
        FFMA2(az[2], wv.y, hb.x); FFMA2(az[3], wv.y, hb.y);
        FFMA2(ah[0], wn,   ha.x); FFMA2(ah[1], wn,   ha.y);
        FFMA2(ah[2], wn,   hb.x); FFMA2(ah[3], wn,   hb.y);
    }

    // epilogue: r,z sigmoid; n = tanh(in + r*hn); h' = n + z*(h_old - n)
    const int j0 = ut * 2;
    // h_old for this tile: lane-low extraction from dup chunks (free: reg alias)
    ulonglong2 hoA0 = *(const ulonglong2*)(hsrc + j0 * 64 + 4 * rt);
    ulonglong2 hoB0 = *(const ulonglong2*)(hsrc + j0 * 64 + 32 + 4 * rt);
    ulonglong2 hoA1 = *(const ulonglong2*)(hsrc + (j0 + 1) * 64 + 4 * rt);
    ulonglong2 hoB1 = *(const ulonglong2*)(hsrc + (j0 + 1) * 64 + 32 + 4 * rt);
    float ho0[4] = { up2(hoA0.x).x, up2(hoA0.y).x, up2(hoB0.x).x, up2(hoB0.y).x };
    float ho1[4] = { up2(hoA1.x).x, up2(hoA1.y).x, up2(hoB1.x).x, up2(hoB1.y).x };

    float o0[4], o1[4];
#pragma unroll
    for (int rr = 0; rr < 4; rr++) {
        float2 arv = up2(ar[rr]), azv = up2(az[rr]);
        float2 aiv = up2(ai[rr]), ahv = up2(ah[rr]);
        {
            float r = sigf(arv.x), z = sigf(azv.x);
            float n = tanhfast(fmaf(r, ahv.x, aiv.x));
            o0[rr] = fmaf(z, ho0[rr] - n, n);
        }
        {
            float r = sigf(arv.y), z = sigf(azv.y);
            float n = tanhfast(fmaf(r, ahv.y, aiv.y));
            o1[rr] = fmaf(z, ho1[rr] - n, n);
        }
    }
    // duplicated stores, de-interleaved chunks
    *(ulonglong2*)(hdst + j0 * 64 + 4 * rt) =
        make_ulonglong2(pk2(o0[0], o0[0]), pk2(o0[1], o0[1]));
    *(ulonglong2*)(hdst + j0 * 64 + 32 + 4 * rt) =
        make_ulonglong2(pk2(o0[2], o0[2]), pk2(o0[3], o0[3]));
    *(ulonglong2*)(hdst + (j0 + 1) * 64 + 4 * rt) =
        make_ulonglong2(pk2(o1[0], o1[0]), pk2(o1[1], o1[1]));
    *(ulonglong2*)(hdst + (j0 + 1) * 64 + 32 + 4 * rt) =
        make_ulonglong2(pk2(o1[2], o1[2]), pk2(o1[3], o1[3]));
}

extern __shared__ float sm[];

__global__ __launch_bounds__(NT, 1)
void gru_kernel(
    const float* __restrict__ x,
    const float* __restrict__ eWih0, const float* __restrict__ eWhh0,
    const float* __restrict__ ebih0, const float* __restrict__ ebhh0,
    const float* __restrict__ eWih1, const float* __restrict__ eWhh1,
    const float* __restrict__ ebih1, const float* __restrict__ ebhh1,
    const float* __restrict__ dWih0, const float* __restrict__ dWhh0,
    const float* __restrict__ dbih0, const float* __restrict__ dbhh0,
    const float* __restrict__ dWih1, const float* __restrict__ dWhh1,
    const float* __restrict__ dbih1, const float* __restrict__ dbhh1,
    const float* __restrict__ outW, const float* __restrict__ outb,
    float* __restrict__ out, int Bn, int TL)
{
    const int tid = threadIdx.x;
    const int b0  = blockIdx.x * ROWS;

    float* Wx0rz = sm + OFF_WX0RZ;  float* Wx0n = sm + OFF_WX0N;
    float* Wh0rz = sm + OFF_WH0RZ;  float* Wh0n = sm + OFF_WH0N;
    float* Wx1rz = sm + OFF_WX1RZ;  float* Wx1n = sm + OFF_WX1N;
    float* Wh1rz = sm + OFF_WH1RZ;  float* Wh1n = sm + OFF_WH1N;
    float* hs0 = sm + OFF_HS0;
    float* hs1 = sm + OFF_HS1;
    float* xs  = sm + OFF_XS;
    float* sOW = sm + OFF_OW;
    float* sOB = sm + OFF_OB;

    const int rt = tid & 7;          // row tile (4 rows)
    const int ut = tid >> 3;         // unit tile (2 units, f32x2 packed)
    const int j0 = ut * 2;

    // ---- stage encoder weights ----
    load_w_split(Wx0rz, Wx0n, eWih0, NINP, tid);
    load_w_split(Wh0rz, Wh0n, eWhh0, Hh, tid);
    load_w_split(Wx1rz, Wx1n, eWih1, Hh, tid);
    load_w_split(Wh1rz, Wh1n, eWhh1, Hh, tid);
    for (int i = tid; i < HBUF; i += NT) {
        hs0[i] = 0.0f; hs0[HBUF + i] = 0.0f;
        hs1[i] = 0.0f; hs1[HBUF + i] = 0.0f;
    }

    // ---- encoder bias pairs in registers ----
    u64 b0r, b0z, b0i, b0h, b1r, b1z, b1i, b1h;
    {
        float2 a, b;
        a = *(const float2*)(ebih0 + j0);        b = *(const float2*)(ebhh0 + j0);
        b0r = pk2(a.x + b.x, a.y + b.y);
        a = *(const float2*)(ebih0 + 64 + j0);   b = *(const float2*)(ebhh0 + 64 + j0);
        b0z = pk2(a.x + b.x, a.y + b.y);
        a = *(const float2*)(ebih0 + 128 + j0);  b0i = pk2(a.x, a.y);
        b = *(const float2*)(ebhh0 + 128 + j0);  b0h = pk2(b.x, b.y);
        a = *(const float2*)(ebih1 + j0);        b = *(const float2*)(ebhh1 + j0);
        b1r = pk2(a.x + b.x, a.y + b.y);
        a = *(const float2*)(ebih1 + 64 + j0);   b = *(const float2*)(ebhh1 + 64 + j0);
        b1z = pk2(a.x + b.x, a.y + b.y);
        a = *(const float2*)(ebih1 + 128 + j0);  b1i = pk2(a.x, a.y);
        b = *(const float2*)(ebhh1 + 128 + j0);  b1h = pk2(b.x, b.y);
    }

    // prestage x for t=0 into buffer 0 (dup layout)
    const int xi = tid >> 5, xr = tid & 31;
    const int xoff = xi * 64 + dup_off(xr);
    if (tid < NINP * ROWS) {
        float v = (b0 + xr < Bn)
            ? x[(size_t)(b0 + xr) * (TSEQ * NINP) + xi] : 0.0f;
        *(u64*)(xs + xoff) = pk2(v, v);
    }
    __syncthreads();

    // ---- encoder: 256 steps ----
    int cur = 0;
    for (int t = 0; t < TSEQ; t++) {
        float xreg = 0.0f;
        if (tid < NINP * ROWS && t + 1 < TSEQ && b0 + xr < Bn)
            xreg = x[(size_t)(b0 + xr) * (TSEQ * NINP) + (size_t)(t + 1) * NINP + xi];
        int nxt = cur ^ 1;
        gru_tile2<NINP>(Wx0rz, Wx0n, Wh0rz, Wh0n,
                        xs + cur * XBUF, hs0 + cur * HBUF, hs0 + nxt * HBUF,
                        b0r, b0z, b0i, b0h, ut, rt);
        if (tid < NINP * ROWS)
            *(u64*)(xs + nxt * XBUF + xoff) = pk2(xreg, xreg);
        __syncthreads();
        gru_tile2<Hh>(Wx1rz, Wx1n, Wh1rz, Wh1n,
                      hs0 + nxt * HBUF, hs1 + cur * HBUF, hs1 + nxt * HBUF,
                      b1r, b1z, b1i, b1h, ut, rt);
        cur = nxt;
        __syncthreads();
    }

    // ---- swap in decoder weights ----
    load_w_split(Wx0rz, Wx0n, dWih0, 1, tid);
    load_w_split(Wh0rz, Wh0n, dWhh0, Hh, tid);
    load_w_split(Wx1rz, Wx1n, dWih1, Hh, tid);
    load_w_split(Wh1rz, Wh1n, dWhh1, Hh, tid);
    if (tid < Hh) sOW[tid] = outW[tid];
    if (tid == 0) sOB[0] = outb[0];
    if (tid < ROWS) *(u64*)(xs + dup_off(tid)) = pk2(0.0f, 0.0f);  // prev cv = 0
    {
        float2 a, b;
        a = *(const float2*)(dbih0 + j0);        b = *(const float2*)(dbhh0 + j0);
        b0r = pk2(a.x + b.x, a.y + b.y);
        a = *(const float2*)(dbih0 + 64 + j0);   b = *(const float2*)(dbhh0 + 64 + j0);
        b0z = pk2(a.x + b.x, a.y + b.y);
        a = *(const float2*)(dbih0 + 128 + j0);  b0i = pk2(a.x, a.y);
        b = *(const float2*)(dbhh0 + 128 + j0);  b0h = pk2(b.x, b.y);
        a = *(const float2*)(dbih1 + j0);        b = *(const float2*)(dbhh1 + j0);
        b1r = pk2(a.x + b.x, a.y + b.y);
        a = *(const float2*)(dbih1 + 64 + j0);   b = *(const float2*)(dbhh1 + 64 + j0);
        b1z = pk2(a.x + b.x, a.y + b.y);
        a = *(const float2*)(dbih1 + 128 + j0);  b1i = pk2(a.x, a.y);
        b = *(const float2*)(dbhh1 + 128 + j0);  b1h = pk2(b.x, b.y);
    }
    __syncthreads();

    // ---- decoder: TL autoregressive steps ----
    for (int s = 0; s < TL; s++) {
        int nxt = cur ^ 1;
        gru_tile2<1>(Wx0rz, Wx0n, Wh0rz, Wh0n,
                     xs, hs0 + cur * HBUF, hs0 + nxt * HBUF,
                     b0r, b0z, b0i, b0h, ut, rt);
        __syncthreads();
        gru_tile2<Hh>(Wx1rz, Wx1n, Wh1rz, Wh1n,
                      hs0 + nxt * HBUF, hs1 + cur * HBUF, hs1 + nxt * HBUF,
                      b1r, b1z, b1i, b1h, ut, rt);
        __syncthreads();
        if (tid < ROWS) {
            float acc = sOB[0];
            const float* hp = hs1 + nxt * HBUF + dup_off(tid);
            #pragma unroll 8
            for (int j = 0; j < Hh; j++)
                acc = fmaf(sOW[j], hp[j * 64], acc);
            if (b0 + tid < Bn)
                out[(size_t)(b0 + tid) * TL + s] = acc;
            *(u64*)(xs + dup_off(tid)) = pk2(acc, acc);
        }
        cur = nxt;
        __syncthreads();
    }
}

extern "C" void kernel_launch(void* const* d_in, const int* in_sizes, int n_in,
                              void* d_out, int out_size) {
    const float* x      = (const float*)d_in[0];
    const float* eWih0  = (const float*)d_in[1];
    const float* eWhh0  = (const float*)d_in[2];
    const float* ebih0  = (const float*)d_in[3];
    const float* ebhh0  = (const float*)d_in[4];
    const float* eWih1  = (const float*)d_in[5];
    const float* eWhh1  = (const float*)d_in[6];
    const float* ebih1  = (const float*)d_in[7];
    const float* ebhh1  = (const float*)d_in[8];
    const float* dWih0  = (const float*)d_in[9];
    const float* dWhh0  = (const float*)d_in[10];
    const float* dbih0  = (const float*)d_in[11];
    const float* dbhh0  = (const float*)d_in[12];
    const float* dWih1  = (const float*)d_in[13];
    const float* dWhh1  = (const float*)d_in[14];
    const float* dbih1  = (const float*)d_in[15];
    const float* dbhh1  = (const float*)d_in[16];
    const float* outW   = (const float*)d_in[17];
    const float* outb   = (const float*)d_in[18];

    int B  = in_sizes[0] / (TSEQ * NINP);
    int TL = out_size / B;                       // 180
    int grid = (B + ROWS - 1) / ROWS;            // 128
    size_t smem = SMEM_FLOATS * sizeof(float);   // ~222 KB

    cudaFuncSetAttribute(gru_kernel,
                         cudaFuncAttributeMaxDynamicSharedMemorySize,
                         (int)smem);

    gru_kernel<<<grid, NT, smem>>>(
        x, eWih0, eWhh0, ebih0, ebhh0, eWih1, eWhh1, ebih1, ebhh1,
        dWih0, dWhh0, dbih0, dbhh0, dWih1, dWhh1, dbih1, dbhh1,
        outW, outb, (float*)d_out, B, TL);
}

// round 12
// speedup vs baseline: 1.4168x; 1.0009x over previous
#include <cuda_runtime.h>

// ---------------------------------------------------------------------------
// GRU encoder-decoder, persistent per-CTA recurrence, f32x2-packed compute.
// R10: duplicated-activation layout, DE-INTERLEAVED so both row-pair loads
// (ha/hb) are LDS.128 at byte 16*rt (banks 4rt..4rt+3 = conflict-free, same
// pattern as the proven R2 h-load). Inner k-body = 4 LDS + 12 FFMA2, zero
// dup-MOVs. Unroll 4 to keep regs ~110. NT=256, tile 2 units x 4 rows.
//
// Dup layout per k-row (64 floats):
//   A chunk rt (floats k*64 + 4rt)      = (v[4rt],v[4rt],v[4rt+1],v[4rt+1])
//   B chunk rt (floats k*64 + 32 + 4rt) = (v[4rt+2],v[4rt+2],v[4rt+3],v[4rt+3])
// Writer for single row r: off = 32*((r>>1)&1) + 4*(r>>2) + 2*(r&1).
// ---------------------------------------------------------------------------

typedef unsigned long long u64;

#define Hh     64
#define G3     192
#define ROWS   32
#define NT     256
#define TSEQ   256
#define NINP   6

// SMEM float offsets
#define OFF_WX0RZ  0        // [6][128]
#define OFF_WX0N   768      // [6][64]
#define OFF_WH0RZ  1152     // [64][128]
#define OFF_WH0N   9344     // [64][64]
#define OFF_WX1RZ  13440    // [64][128]
#define OFF_WX1N   21632    // [64][64]
#define OFF_WH1RZ  25728    // [64][128]
#define OFF_WH1N   33920    // [64][64]
#define OFF_HS0    38016    // [2][64][64] dup, de-interleaved
#define OFF_HS1    46208    // [2][64][64]
#define OFF_XS     54400    // [2][8][64]
#define OFF_OW     55424    // [64]
#define OFF_OB     55488    // [1]
#define SMEM_FLOATS 55492   // 221,968 bytes

#define HBUF 4096
#define XBUF 512

__device__ __forceinline__ u64 pk2(float lo, float hi) {
    u64 r; asm("mov.b64 %0, {%1,%2};" : "=l"(r) : "f"(lo), "f"(hi)); return r;
}
__device__ __forceinline__ float2 up2(u64 v) {
    float2 r; asm("mov.b64 {%0,%1}, %2;" : "=f"(r.x), "=f"(r.y) : "l"(v)); return r;
}
#define FFMA2(acc, a, b) \
    asm("fma.rn.f32x2 %0, %1, %2, %0;" : "+l"(acc) : "l"(a), "l"(b))

__device__ __forceinline__ float sigf(float x) {
    return 1.0f / (1.0f + __expf(-x));
}
__device__ __forceinline__ float tanhfast(float x) {
    float e = __expf(-2.0f * fabsf(x));
    float t = (1.0f - e) / (1.0f + e);
    return copysignf(t, x);
}

// dup-layout float offset within a k-row for single row r
__device__ __forceinline__ int dup_off(int r) {
    return 32 * ((r >> 1) & 1) + 4 * (r >> 2) + 2 * (r & 1);
}

// Split-transpose W[192][K] (row-major) into:
//   rz[k*128 + ut*4 + gate*2 + lane]  (gates r,z)
//   n [k*64  + ut*2 + lane]           (gate n)
__device__ __forceinline__ void load_w_split(float* dstRZ, float* dstN,
                                             const float* __restrict__ src,
                                             int K, int tid) {
    for (int idx = tid; idx < G3 * K; idx += NT) {
        int g = idx / K;
        int k = idx - g * K;
        int gate = g >> 6;          // 0=r,1=z,2=n
        int j    = g & 63;
        int ut   = j >> 1;
        int lane = j & 1;
        float v = src[idx];
        if (gate < 2) dstRZ[k * 128 + ut * 4 + gate * 2 + lane] = v;
        else          dstN [k * 64  + ut * 2 + lane]            = v;
    }
}

// GRU cell for this thread's [2 units (f32x2 packed) x 4 rows] tile.
// xsrc/hsrc/hdst in dup de-interleaved layout (see header).
template<int KIN>
__device__ __forceinline__ void gru_tile2(
    const float* __restrict__ Wxrz, const float* __restrict__ Wxn,
    const float* __restrict__ Whrz, const float* __restrict__ Whn,
    const float* __restrict__ xsrc, const float* __restrict__ hsrc,
    float* __restrict__ hdst,
    u64 br2, u64 bz2, u64 bi2, u64 bh2,
    int ut, int rt)
{
    u64 ar[4], az[4], ai[4], ah[4];
#pragma unroll
    for (int rr = 0; rr < 4; rr++) { ar[rr] = br2; az[rr] = bz2; ai[rr] = bi2; ah[rr] = bh2; }

    const float* wxrz = Wxrz + ut * 4;
    const float* wxn  = Wxn  + ut * 2;
    const float* xpA  = xsrc + 4 * rt;        // rows r0,r0+1 (dup pairs)
    const float* xpB  = xsrc + 32 + 4 * rt;   // rows r0+2,r0+3
#pragma unroll
    for (int k = 0; k < KIN; k++) {
        ulonglong2 ha = *(const ulonglong2*)(xpA + k * 64);
        ulonglong2 hb = *(const ulonglong2*)(xpB + k * 64);
        ulonglong2 wv = *(const ulonglong2*)(wxrz + k * 128);   // (r-pair, z-pair)
        u64 wn = *(const u64*)(wxn + k * 64);
        FFMA2(ar[0], wv.x, ha.x); FFMA2(ar[1], wv.x, ha.y);
        FFMA2(ar[2], wv.x, hb.x); FFMA2(ar[3], wv.x, hb.y);
        FFMA2(az[0], wv.y, ha.x); FFMA2(az[1], wv.y, ha.y);
        FFMA2(az[2], wv.y, hb.x); FFMA2(az[3], wv.y, hb.y);
        FFMA2(ai[0], wn,   ha.x); FFMA2(ai[1], wn,   ha.y);
        FFMA2(ai[2], wn,   hb.x); FFMA2(ai[3], wn,   hb.y);
    }

    const float* whrz = Whrz + ut * 4;
    const float* whn  = Whn  + ut * 2;
    const float* hpA  = hsrc + 4 * rt;
    const float* hpB  = hsrc + 32 + 4 * rt;
#pragma unroll 4
    for (int k = 0; k < Hh; k++) {
        ulonglong2 ha = *(const ulonglong2*)(hpA + k * 64);
        ulonglong2 hb = *(const ulonglong2*)(hpB + k * 64);
        ulonglong2 wv = *(const ulonglong2*)(whrz + k * 128);
        u64 wn = *(const u64*)(whn + k * 64);
        FFMA2(ar[0], wv.x, ha.x); FFMA2(ar[1], wv.x, ha.y);
        FFMA2(ar[2], wv.x, hb.x); FFMA2(ar[3], wv.x, hb.y);
        FFMA2(az[0], wv.y, ha.x); FFMA2(az[1], wv.y, ha.y);
        FFMA2(az[2], wv.y, hb.x); FFMA2(az[3], wv.y, hb.y);
        FFMA2(ah[0], wn,   ha.x); FFMA2(ah[1], wn,   ha.y);
        FFMA2(ah[2], wn,   hb.x); FFMA2(ah[3], wn,   hb.y);
    }

    // epilogue: r,z sigmoid; n = tanh(in + r*hn); h' = n + z*(h_old - n)
    const int j0 = ut * 2;
    // h_old for this tile: lane-low extraction from dup chunks (free: reg alias)
    ulonglong2 hoA0 = *(const ulonglong2*)(hsrc + j0 * 64 + 4 * rt);
    ulonglong2 hoB0 = *(const ulonglong2*)(hsrc + j0 * 64 + 32 + 4 * rt);
    ulonglong2 hoA1 = *(const ulonglong2*)(hsrc + (j0 + 1) * 64 + 4 * rt);
    ulonglong2 hoB1 = *(const ulonglong2*)(hsrc + (j0 + 1) * 64 + 32 + 4 * rt);
    float ho0[4] = { up2(hoA0.x).x, up2(hoA0.y).x, up2(hoB0.x).x, up2(hoB0.y).x };
    float ho1[4] = { up2(hoA1.x).x, up2(hoA1.y).x, up2(hoB1.x).x, up2(hoB1.y).x };

    float o0[4], o1[4];
#pragma unroll
    for (int rr = 0; rr < 4; rr++) {
        float2 arv = up2(ar[rr]), azv = up2(az[rr]);
        float2 aiv = up2(ai[rr]), ahv = up2(ah[rr]);
        {
            float r = sigf(arv.x), z = sigf(azv.x);
            float n = tanhfast(fmaf(r, ahv.x, aiv.x));
            o0[rr] = fmaf(z, ho0[rr] - n, n);
        }
        {
            float r = sigf(arv.y), z = sigf(azv.y);
            float n = tanhfast(fmaf(r, ahv.y, aiv.y));
            o1[rr] = fmaf(z, ho1[rr] - n, n);
        }
    }
    // duplicated stores, de-interleaved chunks
    *(ulonglong2*)(hdst + j0 * 64 + 4 * rt) =
        make_ulonglong2(pk2(o0[0], o0[0]), pk2(o0[1], o0[1]));
    *(ulonglong2*)(hdst + j0 * 64 + 32 + 4 * rt) =
        make_ulonglong2(pk2(o0[2], o0[2]), pk2(o0[3], o0[3]));
    *(ulonglong2*)(hdst + (j0 + 1) * 64 + 4 * rt) =
        make_ulonglong2(pk2(o1[0], o1[0]), pk2(o1[1], o1[1]));
    *(ulonglong2*)(hdst + (j0 + 1) * 64 + 32 + 4 * rt) =
        make_ulonglong2(pk2(o1[2], o1[2]), pk2(o1[3], o1[3]));
}

extern __shared__ float sm[];

__global__ __launch_bounds__(NT, 1)
void gru_kernel(
    const float* __restrict__ x,
    const float* __restrict__ eWih0, const float* __restrict__ eWhh0,
    const float* __restrict__ ebih0, const float* __restrict__ ebhh0,
    const float* __restrict__ eWih1, const float* __restrict__ eWhh1,
    const float* __restrict__ ebih1, const float* __restrict__ ebhh1,
    const float* __restrict__ dWih0, const float* __restrict__ dWhh0,
    const float* __restrict__ dbih0, const float* __restrict__ dbhh0,
    const float* __restrict__ dWih1, const float* __restrict__ dWhh1,
    const float* __restrict__ dbih1, const float* __restrict__ dbhh1,
    const float* __restrict__ outW, const float* __restrict__ outb,
    float* __restrict__ out, int Bn, int TL)
{
    const int tid = threadIdx.x;
    const int b0  = blockIdx.x * ROWS;

    float* Wx0rz = sm + OFF_WX0RZ;  float* Wx0n = sm + OFF_WX0N;
    float* Wh0rz = sm + OFF_WH0RZ;  float* Wh0n = sm + OFF_WH0N;
    float* Wx1rz = sm + OFF_WX1RZ;  float* Wx1n = sm + OFF_WX1N;
    float* Wh1rz = sm + OFF_WH1RZ;  float* Wh1n = sm + OFF_WH1N;
    float* hs0 = sm + OFF_HS0;
    float* hs1 = sm + OFF_HS1;
    float* xs  = sm + OFF_XS;
    float* sOW = sm + OFF_OW;
    float* sOB = sm + OFF_OB;

    const int rt = tid & 7;          // row tile (4 rows)
    const int ut = tid >> 3;         // unit tile (2 units, f32x2 packed)
    const int j0 = ut * 2;

    // ---- stage encoder weights ----
    load_w_split(Wx0rz, Wx0n, eWih0, NINP, tid);
    load_w_split(Wh0rz, Wh0n, eWhh0, Hh, tid);
    load_w_split(Wx1rz, Wx1n, eWih1, Hh, tid);
    load_w_split(Wh1rz, Wh1n, eWhh1, Hh, tid);
    for (int i = tid; i < HBUF; i += NT) {
        hs0[i] = 0.0f; hs0[HBUF + i] = 0.0f;
        hs1[i] = 0.0f; hs1[HBUF + i] = 0.0f;
    }

    // ---- encoder bias pairs in registers ----
    u64 b0r, b0z, b0i, b0h, b1r, b1z, b1i, b1h;
    {
        float2 a, b;
        a = *(const float2*)(ebih0 + j0);        b = *(const float2*)(ebhh0 + j0);
        b0r = pk2(a.x + b.x, a.y + b.y);
        a = *(const float2*)(ebih0 + 64 + j0);   b = *(const float2*)(ebhh0 + 64 + j0);
        b0z = pk2(a.x + b.x, a.y + b.y);
        a = *(const float2*)(ebih0 + 128 + j0);  b0i = pk2(a.x, a.y);
        b = *(const float2*)(ebhh0 + 128 + j0);  b0h = pk2(b.x, b.y);
        a = *(const float2*)(ebih1 + j0);        b = *(const float2*)(ebhh1 + j0);
        b1r = pk2(a.x + b.x, a.y + b.y);
        a = *(const float2*)(ebih1 + 64 + j0);   b = *(const float2*)(ebhh1 + 64 + j0);
        b1z = pk2(a.x + b.x, a.y + b.y);
        a = *(const float2*)(ebih1 + 128 + j0);  b1i = pk2(a.x, a.y);
        b = *(const float2*)(ebhh1 + 128 + j0);  b1h = pk2(b.x, b.y);
    }

    // prestage x for t=0 into buffer 0 (dup layout)
    const int xi = tid >> 5, xr = tid & 31;
    const int xoff = xi * 64 + dup_off(xr);
    if (tid < NINP * ROWS) {
        float v = (b0 + xr < Bn)
            ? x[(size_t)(b0 + xr) * (TSEQ * NINP) + xi] : 0.0f;
        *(u64*)(xs + xoff) = pk2(v, v);
    }
    __syncthreads();

    // ---- encoder: 256 steps ----
    int cur = 0;
    for (int t = 0; t < TSEQ; t++) {
        float xreg = 0.0f;
        if (tid < NINP * ROWS && t + 1 < TSEQ && b0 + xr < Bn)
            xreg = x[(size_t)(b0 + xr) * (TSEQ * NINP) + (size_t)(t + 1) * NINP + xi];
        int nxt = cur ^ 1;
        gru_tile2<NINP>(Wx0rz, Wx0n, Wh0rz, Wh0n,
                        xs + cur * XBUF, hs0 + cur * HBUF, hs0 + nxt * HBUF,
                        b0r, b0z, b0i, b0h, ut, rt);
        if (tid < NINP * ROWS)
            *(u64*)(xs + nxt * XBUF + xoff) = pk2(xreg, xreg);
        __syncthreads();
        gru_tile2<Hh>(Wx1rz, Wx1n, Wh1rz, Wh1n,
                      hs0 + nxt * HBUF, hs1 + cur * HBUF, hs1 + nxt * HBUF,
                      b1r, b1z, b1i, b1h, ut, rt);
        cur = nxt;
        __syncthreads();
    }

    // ---- swap in decoder weights ----
    load_w_split(Wx0rz, Wx0n, dWih0, 1, tid);
    load_w_split(Wh0rz, Wh0n, dWhh0, Hh, tid);
    load_w_split(Wx1rz, Wx1n, dWih1, Hh, tid);
    load_w_split(Wh1rz, Wh1n, dWhh1, Hh, tid);
    if (tid < Hh) sOW[tid] = outW[tid];
    if (tid == 0) sOB[0] = outb[0];
    if (tid < ROWS) *(u64*)(xs + dup_off(tid)) = pk2(0.0f, 0.0f);  // prev cv = 0
    {
        float2 a, b;
        a = *(const float2*)(dbih0 + j0);        b = *(const float2*)(dbhh0 + j0);
        b0r = pk2(a.x + b.x, a.y + b.y);
        a = *(const float2*)(dbih0 + 64 + j0);   b = *(const float2*)(dbhh0 + 64 + j0);
        b0z = pk2(a.x + b.x, a.y + b.y);
        a = *(const float2*)(dbih0 + 128 + j0);  b0i = pk2(a.x, a.y);
        b = *(const float2*)(dbhh0 + 128 + j0);  b0h = pk2(b.x, b.y);
        a = *(const float2*)(dbih1 + j0);        b = *(const float2*)(dbhh1 + j0);
        b1r = pk2(a.x + b.x, a.y + b.y);
        a = *(const float2*)(dbih1 + 64 + j0);   b = *(const float2*)(dbhh1 + 64 + j0);
        b1z = pk2(a.x + b.x, a.y + b.y);
        a = *(const float2*)(dbih1 + 128 + j0);  b1i = pk2(a.x, a.y);
        b = *(const float2*)(dbhh1 + 128 + j0);  b1h = pk2(b.x, b.y);
    }
    __syncthreads();

    // ---- decoder: TL autoregressive steps ----
    for (int s = 0; s < TL; s++) {
        int nxt = cur ^ 1;
        gru_tile2<1>(Wx0rz, Wx0n, Wh0rz, Wh0n,
                     xs, hs0 + cur * HBUF, hs0 + nxt * HBUF,
                     b0r, b0z, b0i, b0h, ut, rt);
        __syncthreads();
        gru_tile2<Hh>(Wx1rz, Wx1n, Wh1rz, Wh1n,
                      hs0 + nxt * HBUF, hs1 + cur * HBUF, hs1 + nxt * HBUF,
                      b1r, b1z, b1i, b1h, ut, rt);
        __syncthreads();
        if (tid < ROWS) {
            float acc = sOB[0];
            const float* hp = hs1 + nxt * HBUF + dup_off(tid);
            #pragma unroll 8
            for (int j = 0; j < Hh; j++)
                acc = fmaf(sOW[j], hp[j * 64], acc);
            if (b0 + tid < Bn)
                out[(size_t)(b0 + tid) * TL + s] = acc;
            *(u64*)(xs + dup_off(tid)) = pk2(acc, acc);
        }
        cur = nxt;
        __syncthreads();
    }
}

extern "C" void kernel_launch(void* const* d_in, const int* in_sizes, int n_in,
                              void* d_out, int out_size) {
    const float* x      = (const float*)d_in[0];
    const float* eWih0  = (const float*)d_in[1];
    const float* eWhh0  = (const float*)d_in[2];
    const float* ebih0  = (const float*)d_in[3];
    const float* ebhh0  = (const float*)d_in[4];
    const float* eWih1  = (const float*)d_in[5];
    const float* eWhh1  = (const float*)d_in[6];
    const float* ebih1  = (const float*)d_in[7];
    const float* ebhh1  = (const float*)d_in[8];
    const float* dWih0  = (const float*)d_in[9];
    const float* dWhh0  = (const float*)d_in[10];
    const float* dbih0  = (const float*)d_in[11];
    const float* dbhh0  = (const float*)d_in[12];
    const float* dWih1  = (const float*)d_in[13];
    const float* dWhh1  = (const float*)d_in[14];
    const float* dbih1  = (const float*)d_in[15];
    const float* dbhh1  = (const float*)d_in[16];
    const float* outW   = (const float*)d_in[17];
    const float* outb   = (const float*)d_in[18];

    int B  = in_sizes[0] / (TSEQ * NINP);
    int TL = out_size / B;                       // 180
    int grid = (B + ROWS - 1) / ROWS;            // 128
    size_t smem = SMEM_FLOATS * sizeof(float);   // ~222 KB

    cudaFuncSetAttribute(gru_kernel,
                         cudaFuncAttributeMaxDynamicSharedMemorySize,
                         (int)smem);

    gru_kernel<<<grid, NT, smem>>>(
        x, eWih0, eWhh0, ebih0, ebhh0, eWih1, eWhh1, ebih1, ebhh1,
        dWih0, dWhh0, dbih0, dbhh0, dWih1, dWhh1, dbih1, dbhh1,
        outW, outb, (float*)d_out, B, TL);
}